// round 1
// baseline (speedup 1.0000x reference)
#include <cuda_runtime.h>
#include <math.h>

// Problem constants
#define BATCH 16
#define HDIM 384
#define WDIM 384
#define HW (HDIM*WDIM)          // 147456
#define NPT 2048
#define DDIM 256
#define NUMK 200
#define CAND_CAP 4096
#define NTILES 32               // 2048/64
#define NPAIRS 528              // 32*33/2

// Scratch (static device globals; allocation-free)
__device__ float g_gray[BATCH*HW];
__device__ float g_p0[BATCH*HW];   // dx*dx
__device__ float g_p1[BATCH*HW];   // dy*dy
__device__ float g_p2[BATCH*HW];   // dx*dy
__device__ float g_t0[BATCH*HW];   // horiz-smoothed
__device__ float g_t1[BATCH*HW];
__device__ float g_t2[BATCH*HW];
__device__ float g_resp[BATCH*HW];
__device__ float g_nms[BATCH*HW];
__device__ float g_norms[BATCH*NPT];
__device__ float g_cval[BATCH*CAND_CAP];
__device__ int   g_cidx[BATCH*CAND_CAP];
__device__ int   g_ccnt[BATCH];
__device__ double g_acc[3];  // 0: sum log1pexp, 1: sum s at corners, 2: sum weighted relu(cos)

// Gaussian-7 weights (float32, matches np computation)
__device__ __constant__ float GW[7] = {
    0.00443304997f, 0.05400558296f, 0.24203622937f, 0.39905027540f,
    0.24203622937f, 0.05400558296f, 0.00443304997f
};

__global__ void k_init() {
    int t = threadIdx.x;
    if (t < 3) g_acc[t] = 0.0;
    if (t < BATCH) g_ccnt[t] = 0;
}

__global__ void k_gray(const float* __restrict__ imgs) {
    int i = blockIdx.x * blockDim.x + threadIdx.x;
    if (i >= BATCH*HW) return;
    int b = i / HW, p = i % HW;
    const float* base = imgs + (size_t)b * 3 * HW;
    g_gray[i] = 0.299f*base[p] + 0.587f*base[HW+p] + 0.114f*base[2*HW+p];
}

// Sobel (edge padding) + structure-tensor products, fused
__global__ void k_gradprod() {
    int i = blockIdx.x * blockDim.x + threadIdx.x;
    if (i >= BATCH*HW) return;
    int b = i / HW, p = i % HW;
    int y = p / WDIM, x = p % WDIM;
    const float* g = g_gray + (size_t)b*HW;
    int ym = y > 0 ? y-1 : 0, yp = y < HDIM-1 ? y+1 : HDIM-1;
    int xm = x > 0 ? x-1 : 0, xp = x < WDIM-1 ? x+1 : WDIM-1;
    float a00 = g[ym*WDIM+xm], a01 = g[ym*WDIM+x], a02 = g[ym*WDIM+xp];
    float a10 = g[y *WDIM+xm],                     a12 = g[y *WDIM+xp];
    float a20 = g[yp*WDIM+xm], a21 = g[yp*WDIM+x], a22 = g[yp*WDIM+xp];
    float dx = (a02 - a00 + 2.f*(a12 - a10) + a22 - a20) * 0.125f;
    float dy = (a20 - a00 + 2.f*(a21 - a01) + a22 - a02) * 0.125f;
    g_p0[i] = dx*dx; g_p1[i] = dy*dy; g_p2[i] = dx*dy;
}

// Separable gaussian, horizontal pass, reflect padding
__global__ void k_gaussh() {
    int i = blockIdx.x * blockDim.x + threadIdx.x;
    if (i >= BATCH*HW) return;
    int p = i % HW;
    int x = p % WDIM;
    int rowbase = i - x;
    float s0 = 0.f, s1 = 0.f, s2 = 0.f;
    #pragma unroll
    for (int v = 0; v < 7; v++) {
        int xx = x + v - 3;
        if (xx < 0) xx = -xx;
        if (xx >= WDIM) xx = 2*WDIM - 2 - xx;
        float w = GW[v];
        s0 += w * g_p0[rowbase + xx];
        s1 += w * g_p1[rowbase + xx];
        s2 += w * g_p2[rowbase + xx];
    }
    g_t0[i] = s0; g_t1[i] = s1; g_t2[i] = s2;
}

// Vertical pass + GFTT response
__global__ void k_gaussv_resp() {
    int i = blockIdx.x * blockDim.x + threadIdx.x;
    if (i >= BATCH*HW) return;
    int b = i / HW, p = i % HW;
    int y = p / WDIM, x = p % WDIM;
    float s0 = 0.f, s1 = 0.f, s2 = 0.f;
    #pragma unroll
    for (int v = 0; v < 7; v++) {
        int yy = y + v - 3;
        if (yy < 0) yy = -yy;
        if (yy >= HDIM) yy = 2*HDIM - 2 - yy;
        int idx = b*HW + yy*WDIM + x;
        float w = GW[v];
        s0 += w * g_t0[idx];
        s1 += w * g_t1[idx];
        s2 += w * g_t2[idx];
    }
    float tr = s0 + s1;
    float det = s0*s1 - s2*s2;
    g_resp[i] = 0.5f * (tr - sqrtf(fabsf(tr*tr - 4.f*det)));
}

// 5x5 NMS (out-of-bounds treated as -inf)
__global__ void k_nms() {
    int i = blockIdx.x * blockDim.x + threadIdx.x;
    if (i >= BATCH*HW) return;
    int b = i / HW, p = i % HW;
    int y = p / WDIM, x = p % WDIM;
    const float* r = g_resp + (size_t)b*HW;
    float v = r[p];
    float m = -INFINITY;
    int y0 = y > 2 ? y-2 : 0, y1 = y < HDIM-3 ? y+2 : HDIM-1;
    int x0 = x > 2 ? x-2 : 0, x1 = x < WDIM-3 ? x+2 : WDIM-1;
    for (int yy = y0; yy <= y1; yy++)
        for (int xx = x0; xx <= x1; xx++)
            m = fmaxf(m, r[yy*WDIM + xx]);
    g_nms[i] = (v == m) ? v : 0.f;
}

// Per non-overlapping 8x8 block: keep elements == block max and > 0; emit candidates
__global__ void k_cand() {
    int gw = (blockIdx.x * blockDim.x + threadIdx.x) >> 5;
    int lane = threadIdx.x & 31;
    const int BPB = (HDIM/8) * (WDIM/8);  // 2304
    if (gw >= BATCH * BPB) return;
    int b = gw / BPB, blk = gw % BPB;
    int by = blk / (WDIM/8), bx = blk % (WDIM/8);
    int y0 = by*8, x0 = bx*8;
    float v[2]; int pp[2];
    #pragma unroll
    for (int t = 0; t < 2; t++) {
        int e = lane + 32*t;
        int ly = e >> 3, lx = e & 7;
        int p = (y0+ly)*WDIM + (x0+lx);
        pp[t] = p;
        v[t] = g_nms[(size_t)b*HW + p];
    }
    float m = fmaxf(v[0], v[1]);
    #pragma unroll
    for (int off = 16; off > 0; off >>= 1)
        m = fmaxf(m, __shfl_xor_sync(0xFFFFFFFFu, m, off));
    #pragma unroll
    for (int t = 0; t < 2; t++) {
        if (v[t] == m && v[t] > 0.f) {
            int pos = atomicAdd(&g_ccnt[b], 1);
            if (pos < CAND_CAP) {
                g_cval[b*CAND_CAP + pos] = v[t];
                g_cidx[b*CAND_CAP + pos] = pp[t];
            }
        }
    }
}

// Per-batch top-200 (value desc, index asc) via bitonic sort; accumulate sum of s at corners
__global__ void __launch_bounds__(1024) k_topk(const float* __restrict__ sd) {
    __shared__ unsigned long long keys[CAND_CAP];
    int b = blockIdx.x;
    int tid = threadIdx.x;
    int n = g_ccnt[b]; if (n > CAND_CAP) n = CAND_CAP;
    for (int i = tid; i < CAND_CAP; i += 1024) {
        unsigned long long kk = 0ull;
        if (i < n) {
            unsigned int vb = __float_as_uint(g_cval[b*CAND_CAP + i]);  // values > 0
            kk = ((unsigned long long)vb << 32) | (unsigned long long)(0xFFFFFFFFu - (unsigned)g_cidx[b*CAND_CAP + i]);
        }
        keys[i] = kk;
    }
    __syncthreads();
    for (int k = 2; k <= CAND_CAP; k <<= 1) {
        for (int j = k >> 1; j > 0; j >>= 1) {
            for (int i = tid; i < CAND_CAP; i += 1024) {
                int ixj = i ^ j;
                if (ixj > i) {
                    bool descend = ((i & k) == 0);
                    unsigned long long a = keys[i], c = keys[ixj];
                    if (descend ? (a < c) : (a > c)) { keys[i] = c; keys[ixj] = a; }
                }
            }
            __syncthreads();
        }
    }
    int take = n < NUMK ? n : NUMK;
    double s = 0.0;
    if (tid < take) {
        unsigned idx = 0xFFFFFFFFu - (unsigned)(keys[tid] & 0xFFFFFFFFull);
        s = (double)sd[(size_t)b*HW + idx];
    }
    // block reduce
    __shared__ double red[32];
    #pragma unroll
    for (int off = 16; off > 0; off >>= 1) s += __shfl_xor_sync(0xFFFFFFFFu, s, off);
    if ((tid & 31) == 0) red[tid >> 5] = s;
    __syncthreads();
    if (tid < 32) {
        double v = red[tid];
        #pragma unroll
        for (int off = 16; off > 0; off >>= 1) v += __shfl_xor_sync(0xFFFFFFFFu, v, off);
        if (tid == 0) atomicAdd(&g_acc[1], v);
    }
}

// sum over all of logaddexp(0, s)
__global__ void k_logexp(const float* __restrict__ sd) {
    double s = 0.0;
    int stride = gridDim.x * blockDim.x;
    for (int i = blockIdx.x * blockDim.x + threadIdx.x; i < BATCH*HW; i += stride) {
        float v = sd[i];
        s += (double)(fmaxf(v, 0.f) + log1pf(expf(-fabsf(v))));
    }
    __shared__ double red[8];
    #pragma unroll
    for (int off = 16; off > 0; off >>= 1) s += __shfl_xor_sync(0xFFFFFFFFu, s, off);
    int t = threadIdx.x;
    if ((t & 31) == 0) red[t >> 5] = s;
    __syncthreads();
    if (t < 8) {
        double v = red[t];
        #pragma unroll
        for (int off = 4; off > 0; off >>= 1) v += __shfl_xor_sync(0xFFu, v, off);
        if (t == 0) atomicAdd(&g_acc[0], v);
    }
}

// Row norms of descriptors
__global__ void k_norms(const float* __restrict__ desc) {
    int gw = (blockIdx.x * blockDim.x + threadIdx.x) >> 5;
    int lane = threadIdx.x & 31;
    if (gw >= BATCH*NPT) return;
    const float* p = desc + (size_t)gw * DDIM;
    float s = 0.f;
    #pragma unroll
    for (int t = 0; t < 8; t++) { float v = p[lane + 32*t]; s += v*v; }
    #pragma unroll
    for (int off = 16; off > 0; off >>= 1) s += __shfl_xor_sync(0xFFFFFFFFu, s, off);
    if (lane == 0) g_norms[gw] = sqrtf(s);
}

// Symmetric cosine-similarity GEMM + relu-sum. Tile 64x64, only tj >= ti pairs.
__global__ void __launch_bounds__(256) k_gemm(const float* __restrict__ desc) {
    __shared__ __align__(16) float As[16][68];
    __shared__ __align__(16) float Bs[16][68];
    int b = blockIdx.y;
    // decode pair index -> (ti, tj), tj >= ti
    int ti = 0, rem = blockIdx.x;
    while (rem >= NTILES - ti) { rem -= NTILES - ti; ti++; }
    int tj = ti + rem;

    int t = threadIdx.x;
    int tx = t & 15, ty = t >> 4;
    int row = t >> 2, seg = t & 3;
    const float* Abase = desc + ((size_t)b*NPT + ti*64) * DDIM;
    const float* Bbase = desc + ((size_t)b*NPT + tj*64) * DDIM;

    float acc[4][4];
    #pragma unroll
    for (int i = 0; i < 4; i++)
        #pragma unroll
        for (int j = 0; j < 4; j++) acc[i][j] = 0.f;

    for (int kk = 0; kk < DDIM; kk += 16) {
        float4 va = *(const float4*)(Abase + (size_t)row*DDIM + kk + seg*4);
        float4 vb = *(const float4*)(Bbase + (size_t)row*DDIM + kk + seg*4);
        As[seg*4+0][row] = va.x; As[seg*4+1][row] = va.y;
        As[seg*4+2][row] = va.z; As[seg*4+3][row] = va.w;
        Bs[seg*4+0][row] = vb.x; Bs[seg*4+1][row] = vb.y;
        Bs[seg*4+2][row] = vb.z; Bs[seg*4+3][row] = vb.w;
        __syncthreads();
        #pragma unroll
        for (int k = 0; k < 16; k++) {
            float4 a = *(const float4*)&As[k][ty*4];
            float4 bb = *(const float4*)&Bs[k][tx*4];
            float av[4] = {a.x, a.y, a.z, a.w};
            float bv[4] = {bb.x, bb.y, bb.z, bb.w};
            #pragma unroll
            for (int i = 0; i < 4; i++)
                #pragma unroll
                for (int j = 0; j < 4; j++)
                    acc[i][j] = fmaf(av[i], bv[j], acc[i][j]);
        }
        __syncthreads();
    }

    // epilogue: cosine, relu, symmetry weight, accumulate
    int gi0 = ti*64 + ty*4, gj0 = tj*64 + tx*4;
    const float* nb = g_norms + b*NPT;
    double s = 0.0;
    #pragma unroll
    for (int i = 0; i < 4; i++) {
        float ni = nb[gi0 + i];
        #pragma unroll
        for (int j = 0; j < 4; j++) {
            float nj = nb[gj0 + j];
            float c = acc[i][j] / fmaxf(ni*nj, 1e-8f);
            float r = c > 0.f ? c : 0.f;
            float w;
            if (ti == tj) {
                int gi = gi0 + i, gj = gj0 + j;
                w = (gi < gj) ? 2.f : (gi == gj ? 1.f : 0.f);
            } else w = 2.f;
            s += (double)(w * r);
        }
    }
    __shared__ double red[8];
    #pragma unroll
    for (int off = 16; off > 0; off >>= 1) s += __shfl_xor_sync(0xFFFFFFFFu, s, off);
    if ((t & 31) == 0) red[t >> 5] = s;
    __syncthreads();
    if (t < 8) {
        double v = red[t];
        #pragma unroll
        for (int off = 4; off > 0; off >>= 1) v += __shfl_xor_sync(0xFFu, v, off);
        if (t == 0) atomicAdd(&g_acc[2], v);
    }
}

__global__ void k_final(float* out) {
    double bce = (g_acc[0] - g_acc[1]) / (double)((size_t)BATCH * HW);
    double rel = g_acc[2] / ((double)BATCH * (double)NPT * (double)NPT);
    out[0] = (float)(bce + rel);
}

extern "C" void kernel_launch(void* const* d_in, const int* in_sizes, int n_in,
                              void* d_out, int out_size) {
    const float* desc = (const float*)d_in[0];
    // d_in[1] = scores (unused by the reference loss)
    const float* sd   = (const float*)d_in[2];
    const float* imgs = (const float*)d_in[3];
    float* out = (float*)d_out;

    const int PIX = BATCH * HW;
    const int TPB = 256;
    const int GP = (PIX + TPB - 1) / TPB;

    k_init<<<1, 32>>>();
    k_gray<<<GP, TPB>>>(imgs);
    k_gradprod<<<GP, TPB>>>();
    k_gaussh<<<GP, TPB>>>();
    k_gaussv_resp<<<GP, TPB>>>();
    k_nms<<<GP, TPB>>>();
    {
        const int warps = BATCH * (HDIM/8) * (WDIM/8);       // 36864
        k_cand<<<(warps*32 + TPB - 1) / TPB, TPB>>>();
    }
    k_topk<<<BATCH, 1024>>>(sd);
    k_logexp<<<1024, TPB>>>(sd);
    {
        const int warps = BATCH * NPT;                       // 32768
        k_norms<<<(warps*32 + TPB - 1) / TPB, TPB>>>(desc);
    }
    {
        dim3 grid(NPAIRS, BATCH);
        k_gemm<<<grid, 256>>>(desc);
    }
    k_final<<<1, 1>>>(out);
    (void)in_sizes; (void)n_in; (void)out_size;
}

// round 5
// speedup vs baseline: 1.8796x; 1.8796x over previous
#include <cuda_runtime.h>
#include <cuda_bf16.h>
#include <math.h>
#include <cstdint>

// Problem constants
#define BATCH 16
#define HDIM 384
#define WDIM 384
#define HW (HDIM*WDIM)          // 147456
#define NPT 2048
#define DDIM 256
#define NUMK 200
#define CAND_CAP 4096

// GEMM tiling (HMMA mma.sync path; tcgen05 unavailable: harness compiles for compute_103 non-'a')
#define TM 128
#define TN 128
#define KC 64                   // bf16 per K-chunk (128 bytes/row)
#define NCHUNK (DDIM/KC)        // 4
#define NT2 (NPT/TM)            // 16
#define NPAIRS2 (NT2*(NT2+1)/2) // 136

// Scratch (static device globals; allocation-free)
__device__ float g_gray[BATCH*HW];
__device__ float g_p0[BATCH*HW];
__device__ float g_p1[BATCH*HW];
__device__ float g_p2[BATCH*HW];
__device__ float g_t0[BATCH*HW];
__device__ float g_t1[BATCH*HW];
__device__ float g_t2[BATCH*HW];
__device__ float g_resp[BATCH*HW];
__device__ float g_nms[BATCH*HW];
__device__ float g_cval[BATCH*CAND_CAP];
__device__ int   g_cidx[BATCH*CAND_CAP];
__device__ int   g_ccnt[BATCH];
__device__ double g_acc[3];  // 0: sum log1pexp, 1: sum s at corners, 2: sum weighted relu(cos)
__device__ __nv_bfloat16 g_descbf[(size_t)BATCH*NPT*DDIM];  // 16MB normalized bf16

__device__ __constant__ float GW[7] = {
    0.00443304997f, 0.05400558296f, 0.24203622937f, 0.39905027540f,
    0.24203622937f, 0.05400558296f, 0.00443304997f
};

#define SMEM_SWIZZLE_128B(byte_offset) \
    ((byte_offset) ^ (((byte_offset) >> 3) & 0x70))

__device__ __forceinline__ uint32_t smem_to_u32(const void* smem_ptr) {
    uint32_t addr;
    asm("{ .reg .u64 tmp; cvta.to.shared.u64 tmp, %1; cvt.u32.u64 %0, tmp; }"
        : "=r"(addr) : "l"(smem_ptr));
    return addr;
}
__device__ __forceinline__ void ldm_x4(uint32_t& r0, uint32_t& r1, uint32_t& r2, uint32_t& r3,
                                       uint32_t addr) {
    asm volatile("ldmatrix.sync.aligned.m8n8.x4.shared.b16 {%0,%1,%2,%3}, [%4];"
                 : "=r"(r0), "=r"(r1), "=r"(r2), "=r"(r3) : "r"(addr));
}
__device__ __forceinline__ void mma_bf16(float* c, const uint32_t* a, uint32_t b0, uint32_t b1) {
    asm volatile(
        "mma.sync.aligned.m16n8k16.row.col.f32.bf16.bf16.f32 "
        "{%0,%1,%2,%3}, {%4,%5,%6,%7}, {%8,%9}, {%0,%1,%2,%3};"
        : "+f"(c[0]), "+f"(c[1]), "+f"(c[2]), "+f"(c[3])
        : "r"(a[0]), "r"(a[1]), "r"(a[2]), "r"(a[3]), "r"(b0), "r"(b1));
}

// ==================== image pipeline ====================
__global__ void k_init() {
    int t = threadIdx.x;
    if (t < 3) g_acc[t] = 0.0;
    if (t < BATCH) g_ccnt[t] = 0;
}

__global__ void k_gray(const float* __restrict__ imgs) {
    int i = blockIdx.x * blockDim.x + threadIdx.x;
    if (i >= BATCH*HW) return;
    int b = i / HW, p = i % HW;
    const float* base = imgs + (size_t)b * 3 * HW;
    g_gray[i] = 0.299f*base[p] + 0.587f*base[HW+p] + 0.114f*base[2*HW+p];
}

__global__ void k_gradprod() {
    int i = blockIdx.x * blockDim.x + threadIdx.x;
    if (i >= BATCH*HW) return;
    int b = i / HW, p = i % HW;
    int y = p / WDIM, x = p % WDIM;
    const float* g = g_gray + (size_t)b*HW;
    int ym = y > 0 ? y-1 : 0, yp = y < HDIM-1 ? y+1 : HDIM-1;
    int xm = x > 0 ? x-1 : 0, xp = x < WDIM-1 ? x+1 : WDIM-1;
    float a00 = g[ym*WDIM+xm], a01 = g[ym*WDIM+x], a02 = g[ym*WDIM+xp];
    float a10 = g[y *WDIM+xm],                     a12 = g[y *WDIM+xp];
    float a20 = g[yp*WDIM+xm], a21 = g[yp*WDIM+x], a22 = g[yp*WDIM+xp];
    float dx = (a02 - a00 + 2.f*(a12 - a10) + a22 - a20) * 0.125f;
    float dy = (a20 - a00 + 2.f*(a21 - a01) + a22 - a02) * 0.125f;
    g_p0[i] = dx*dx; g_p1[i] = dy*dy; g_p2[i] = dx*dy;
}

__global__ void k_gaussh() {
    int i = blockIdx.x * blockDim.x + threadIdx.x;
    if (i >= BATCH*HW) return;
    int p = i % HW;
    int x = p % WDIM;
    int rowbase = i - x;
    float s0 = 0.f, s1 = 0.f, s2 = 0.f;
    #pragma unroll
    for (int v = 0; v < 7; v++) {
        int xx = x + v - 3;
        if (xx < 0) xx = -xx;
        if (xx >= WDIM) xx = 2*WDIM - 2 - xx;
        float w = GW[v];
        s0 += w * g_p0[rowbase + xx];
        s1 += w * g_p1[rowbase + xx];
        s2 += w * g_p2[rowbase + xx];
    }
    g_t0[i] = s0; g_t1[i] = s1; g_t2[i] = s2;
}

__global__ void k_gaussv_resp() {
    int i = blockIdx.x * blockDim.x + threadIdx.x;
    if (i >= BATCH*HW) return;
    int b = i / HW, p = i % HW;
    int y = p / WDIM, x = p % WDIM;
    float s0 = 0.f, s1 = 0.f, s2 = 0.f;
    #pragma unroll
    for (int v = 0; v < 7; v++) {
        int yy = y + v - 3;
        if (yy < 0) yy = -yy;
        if (yy >= HDIM) yy = 2*HDIM - 2 - yy;
        int idx = b*HW + yy*WDIM + x;
        float w = GW[v];
        s0 += w * g_t0[idx];
        s1 += w * g_t1[idx];
        s2 += w * g_t2[idx];
    }
    float tr = s0 + s1;
    float det = s0*s1 - s2*s2;
    g_resp[i] = 0.5f * (tr - sqrtf(fabsf(tr*tr - 4.f*det)));
}

__global__ void k_nms() {
    int i = blockIdx.x * blockDim.x + threadIdx.x;
    if (i >= BATCH*HW) return;
    int b = i / HW, p = i % HW;
    int y = p / WDIM, x = p % WDIM;
    const float* r = g_resp + (size_t)b*HW;
    float v = r[p];
    float m = -INFINITY;
    int y0 = y > 2 ? y-2 : 0, y1 = y < HDIM-3 ? y+2 : HDIM-1;
    int x0 = x > 2 ? x-2 : 0, x1 = x < WDIM-3 ? x+2 : WDIM-1;
    for (int yy = y0; yy <= y1; yy++)
        for (int xx = x0; xx <= x1; xx++)
            m = fmaxf(m, r[yy*WDIM + xx]);
    g_nms[i] = (v == m) ? v : 0.f;
}

__global__ void k_cand() {
    int gw = (blockIdx.x * blockDim.x + threadIdx.x) >> 5;
    int lane = threadIdx.x & 31;
    const int BPB = (HDIM/8) * (WDIM/8);  // 2304
    if (gw >= BATCH * BPB) return;
    int b = gw / BPB, blk = gw % BPB;
    int by = blk / (WDIM/8), bx = blk % (WDIM/8);
    int y0 = by*8, x0 = bx*8;
    float v[2]; int pp[2];
    #pragma unroll
    for (int t = 0; t < 2; t++) {
        int e = lane + 32*t;
        int ly = e >> 3, lx = e & 7;
        int p = (y0+ly)*WDIM + (x0+lx);
        pp[t] = p;
        v[t] = g_nms[(size_t)b*HW + p];
    }
    float m = fmaxf(v[0], v[1]);
    #pragma unroll
    for (int off = 16; off > 0; off >>= 1)
        m = fmaxf(m, __shfl_xor_sync(0xFFFFFFFFu, m, off));
    #pragma unroll
    for (int t = 0; t < 2; t++) {
        if (v[t] == m && v[t] > 0.f) {
            int pos = atomicAdd(&g_ccnt[b], 1);
            if (pos < CAND_CAP) {
                g_cval[b*CAND_CAP + pos] = v[t];
                g_cidx[b*CAND_CAP + pos] = pp[t];
            }
        }
    }
}

__global__ void __launch_bounds__(1024) k_topk(const float* __restrict__ sd) {
    __shared__ unsigned long long keys[CAND_CAP];
    int b = blockIdx.x;
    int tid = threadIdx.x;
    int n = g_ccnt[b]; if (n > CAND_CAP) n = CAND_CAP;
    for (int i = tid; i < CAND_CAP; i += 1024) {
        unsigned long long kk = 0ull;
        if (i < n) {
            unsigned int vb = __float_as_uint(g_cval[b*CAND_CAP + i]);
            kk = ((unsigned long long)vb << 32) | (unsigned long long)(0xFFFFFFFFu - (unsigned)g_cidx[b*CAND_CAP + i]);
        }
        keys[i] = kk;
    }
    __syncthreads();
    for (int k = 2; k <= CAND_CAP; k <<= 1) {
        for (int j = k >> 1; j > 0; j >>= 1) {
            for (int i = tid; i < CAND_CAP; i += 1024) {
                int ixj = i ^ j;
                if (ixj > i) {
                    bool descend = ((i & k) == 0);
                    unsigned long long a = keys[i], c = keys[ixj];
                    if (descend ? (a < c) : (a > c)) { keys[i] = c; keys[ixj] = a; }
                }
            }
            __syncthreads();
        }
    }
    int take = n < NUMK ? n : NUMK;
    double s = 0.0;
    if (tid < take) {
        unsigned idx = 0xFFFFFFFFu - (unsigned)(keys[tid] & 0xFFFFFFFFull);
        s = (double)sd[(size_t)b*HW + idx];
    }
    __shared__ double red[32];
    #pragma unroll
    for (int off = 16; off > 0; off >>= 1) s += __shfl_xor_sync(0xFFFFFFFFu, s, off);
    if ((tid & 31) == 0) red[tid >> 5] = s;
    __syncthreads();
    if (tid < 32) {
        double v = red[tid];
        #pragma unroll
        for (int off = 16; off > 0; off >>= 1) v += __shfl_xor_sync(0xFFFFFFFFu, v, off);
        if (tid == 0) atomicAdd(&g_acc[1], v);
    }
}

__global__ void k_logexp(const float* __restrict__ sd) {
    double s = 0.0;
    int stride = gridDim.x * blockDim.x;
    for (int i = blockIdx.x * blockDim.x + threadIdx.x; i < BATCH*HW; i += stride) {
        float v = sd[i];
        s += (double)(fmaxf(v, 0.f) + log1pf(expf(-fabsf(v))));
    }
    __shared__ double red[8];
    #pragma unroll
    for (int off = 16; off > 0; off >>= 1) s += __shfl_xor_sync(0xFFFFFFFFu, s, off);
    int t = threadIdx.x;
    if ((t & 31) == 0) red[t >> 5] = s;
    __syncthreads();
    if (t < 8) {
        double v = red[t];
        #pragma unroll
        for (int off = 4; off > 0; off >>= 1) v += __shfl_xor_sync(0xFFu, v, off);
        if (t == 0) atomicAdd(&g_acc[0], v);
    }
}

// ==================== descriptor prep: normalize -> bf16 ====================
__global__ void k_prep(const float* __restrict__ desc) {
    int gw = (blockIdx.x * blockDim.x + threadIdx.x) >> 5;
    int lane = threadIdx.x & 31;
    if (gw >= BATCH*NPT) return;
    const float* p = desc + (size_t)gw * DDIM;
    float v[8]; float s = 0.f;
    #pragma unroll
    for (int t = 0; t < 8; t++) { v[t] = p[lane + 32*t]; s += v[t]*v[t]; }
    #pragma unroll
    for (int off = 16; off > 0; off >>= 1) s += __shfl_xor_sync(0xFFFFFFFFu, s, off);
    float inv = 1.f / fmaxf(sqrtf(s), 1e-8f);
    __nv_bfloat16* q = g_descbf + (size_t)gw * DDIM;
    #pragma unroll
    for (int t = 0; t < 8; t++) q[lane + 32*t] = __float2bfloat16(v[t] * inv);
}

// ==================== bf16 HMMA symmetric GEMM ====================
// CTA 128x128, 8 warps (2x4), warp = 64x32 via m16n8k16.
__global__ void __launch_bounds__(256) k_gemm_mma() {
    __shared__ __align__(128) char sA[TM*128];
    __shared__ __align__(128) char sB[TN*128];
    __shared__ double red[8];

    int tid = threadIdx.x, wid = tid >> 5, lane = tid & 31;
    int wm = wid & 1, wn = wid >> 1;       // warp grid 2(M) x 4(N)
    int b = blockIdx.y;
    int ti = 0, rem = blockIdx.x;
    while (rem >= NT2 - ti) { rem -= NT2 - ti; ti++; }
    int tj = ti + rem;

    const __nv_bfloat16* Abase = g_descbf + ((size_t)b*NPT + (size_t)ti*TM) * DDIM;
    const __nv_bfloat16* Bbase = g_descbf + ((size_t)b*NPT + (size_t)tj*TM) * DDIM;

    uint32_t sAu = smem_to_u32(sA), sBu = smem_to_u32(sB);

    // per-lane ldmatrix base offsets (row = l&15 within 16-row tile, khalf = l>>4)
    int lrow = lane & 15, lkh = lane >> 4;

    float acc[4][4][4];
    #pragma unroll
    for (int i = 0; i < 4; i++)
        #pragma unroll
        for (int j = 0; j < 4; j++)
            #pragma unroll
            for (int c = 0; c < 4; c++) acc[i][j][c] = 0.f;

    // cooperative-load indexing
    int ldrow = tid >> 3, ldseg = tid & 7;

    for (int kc = 0; kc < NCHUNK; kc++) {
        // load A,B chunk tiles: 128 rows x 128 bytes, SW128 swizzled
        #pragma unroll
        for (int u = 0; u < 4; u++) {
            int row = ldrow + u*32;
            uint32_t off = SMEM_SWIZZLE_128B((uint32_t)(row*128 + ldseg*16));
            *(uint4*)(sA + off) = *(const uint4*)(Abase + (size_t)row*DDIM + kc*KC + ldseg*8);
            *(uint4*)(sB + off) = *(const uint4*)(Bbase + (size_t)row*DDIM + kc*KC + ldseg*8);
        }
        __syncthreads();

        #pragma unroll
        for (int ks = 0; ks < 4; ks++) {
            // B fragments: 2 n16-pairs
            uint32_t bf[2][4];
            #pragma unroll
            for (int np = 0; np < 2; np++) {
                int row = wn*32 + np*16 + lrow;
                uint32_t off = SMEM_SWIZZLE_128B((uint32_t)(row*128 + ks*32 + lkh*16));
                ldm_x4(bf[np][0], bf[np][1], bf[np][2], bf[np][3], sBu + off);
            }
            // A fragments: 4 m16 tiles
            uint32_t af[4][4];
            #pragma unroll
            for (int i = 0; i < 4; i++) {
                int row = wm*64 + i*16 + lrow;
                uint32_t off = SMEM_SWIZZLE_128B((uint32_t)(row*128 + ks*32 + lkh*16));
                ldm_x4(af[i][0], af[i][1], af[i][2], af[i][3], sAu + off);
            }
            #pragma unroll
            for (int i = 0; i < 4; i++)
                #pragma unroll
                for (int j = 0; j < 4; j++) {
                    int np = j >> 1, h = j & 1;
                    mma_bf16(acc[i][j], af[i], bf[np][h], bf[np][h + 2]);
                }
        }
        __syncthreads();
    }

    // epilogue: relu + symmetry weight + reduce
    double s = 0.0;
    int gi_base = ti*TM + wm*64;
    int gj_base = tj*TN + wn*32;
    int r0 = lane >> 2, c0 = (lane & 3) * 2;
    #pragma unroll
    for (int i = 0; i < 4; i++) {
        #pragma unroll
        for (int j = 0; j < 4; j++) {
            #pragma unroll
            for (int c = 0; c < 4; c++) {
                float v = acc[i][j][c];
                float r = v > 0.f ? v : 0.f;
                if (ti != tj) {
                    s += (double)(2.f * r);
                } else {
                    int gi = gi_base + i*16 + r0 + ((c >> 1) ? 8 : 0);
                    int gj = gj_base + j*8 + c0 + (c & 1);
                    float w = (gi < gj) ? 2.f : (gi == gj ? 1.f : 0.f);
                    s += (double)(w * r);
                }
            }
        }
    }
    #pragma unroll
    for (int off = 16; off > 0; off >>= 1) s += __shfl_xor_sync(0xFFFFFFFFu, s, off);
    if (lane == 0) red[wid] = s;
    __syncthreads();
    if (tid < 8) {
        double v = red[tid];
        #pragma unroll
        for (int off = 4; off > 0; off >>= 1) v += __shfl_xor_sync(0xFFu, v, off);
        if (tid == 0) atomicAdd(&g_acc[2], v);
    }
}

__global__ void k_final(float* out) {
    double bce = (g_acc[0] - g_acc[1]) / (double)((size_t)BATCH * HW);
    double rel = g_acc[2] / ((double)BATCH * (double)NPT * (double)NPT);
    out[0] = (float)(bce + rel);
}

extern "C" void kernel_launch(void* const* d_in, const int* in_sizes, int n_in,
                              void* d_out, int out_size) {
    const float* desc = (const float*)d_in[0];
    // d_in[1] = scores (unused by the reference loss)
    const float* sd   = (const float*)d_in[2];
    const float* imgs = (const float*)d_in[3];
    float* out = (float*)d_out;

    const int PIX = BATCH * HW;
    const int TPB = 256;
    const int GP = (PIX + TPB - 1) / TPB;

    k_init<<<1, 32>>>();
    k_gray<<<GP, TPB>>>(imgs);
    k_gradprod<<<GP, TPB>>>();
    k_gaussh<<<GP, TPB>>>();
    k_gaussv_resp<<<GP, TPB>>>();
    k_nms<<<GP, TPB>>>();
    {
        const int warps = BATCH * (HDIM/8) * (WDIM/8);       // 36864
        k_cand<<<(warps*32 + TPB - 1) / TPB, TPB>>>();
    }
    k_topk<<<BATCH, 1024>>>(sd);
    k_logexp<<<1024, TPB>>>(sd);
    {
        const int warps = BATCH * NPT;                       // 32768
        k_prep<<<(warps*32 + TPB - 1) / TPB, TPB>>>(desc);
    }
    {
        dim3 grid(NPAIRS2, BATCH);
        k_gemm_mma<<<grid, 256>>>();
    }
    k_final<<<1, 1>>>(out);
    (void)in_sizes; (void)n_in; (void)out_size;
}

// round 7
// speedup vs baseline: 2.1833x; 1.1616x over previous
#include <cuda_runtime.h>
#include <cuda_bf16.h>
#include <math.h>
#include <cstdint>

// Problem constants
#define BATCH 16
#define HDIM 384
#define WDIM 384
#define HW (HDIM*WDIM)          // 147456
#define NPT 2048
#define DDIM 256
#define NUMK 200
#define CAND_CAP 4096

// GEMM tiling (HMMA mma.sync path; tcgen05 unavailable: harness targets compute_103 non-'a')
#define TM 128
#define TN 128
#define KC 64                   // bf16 per K-chunk (128 bytes/row)
#define NCHUNK (DDIM/KC)        // 4
#define NT2 (NPT/TM)            // 16
#define NPAIRS2 (NT2*(NT2+1)/2) // 136
#define STAGE_BYTES (TM*128)    // 16KB per tile per stage

// Scratch (static device globals; allocation-free)
__device__ float g_resp[BATCH*HW];
__device__ float g_cval[BATCH*CAND_CAP];
__device__ int   g_cidx[BATCH*CAND_CAP];
__device__ int   g_ccnt[BATCH];
__device__ double g_acc[3];  // 0: sum log1pexp, 1: sum s at corners, 2: sum weighted relu(cos)
__device__ __nv_bfloat16 g_descbf[(size_t)BATCH*NPT*DDIM];  // 16MB normalized bf16

__device__ __constant__ float GW[7] = {
    0.00443304997f, 0.05400558296f, 0.24203622937f, 0.39905027540f,
    0.24203622937f, 0.05400558296f, 0.00443304997f
};

#define SMEM_SWIZZLE_128B(byte_offset) \
    ((byte_offset) ^ (((byte_offset) >> 3) & 0x70))

__device__ __forceinline__ int rfl(int i, int n) {
    if (i < 0) i = -i;
    if (i >= n) i = 2*n - 2 - i;
    return i;
}
__device__ __forceinline__ uint32_t smem_to_u32(const void* smem_ptr) {
    uint32_t addr;
    asm("{ .reg .u64 tmp; cvta.to.shared.u64 tmp, %1; cvt.u32.u64 %0, tmp; }"
        : "=r"(addr) : "l"(smem_ptr));
    return addr;
}
__device__ __forceinline__ void ldm_x4(uint32_t& r0, uint32_t& r1, uint32_t& r2, uint32_t& r3,
                                       uint32_t addr) {
    asm volatile("ldmatrix.sync.aligned.m8n8.x4.shared.b16 {%0,%1,%2,%3}, [%4];"
                 : "=r"(r0), "=r"(r1), "=r"(r2), "=r"(r3) : "r"(addr));
}
__device__ __forceinline__ void mma_bf16(float* c, const uint32_t* a, uint32_t b0, uint32_t b1) {
    asm volatile(
        "mma.sync.aligned.m16n8k16.row.col.f32.bf16.bf16.f32 "
        "{%0,%1,%2,%3}, {%4,%5,%6,%7}, {%8,%9}, {%0,%1,%2,%3};"
        : "+f"(c[0]), "+f"(c[1]), "+f"(c[2]), "+f"(c[3])
        : "r"(a[0]), "r"(a[1]), "r"(a[2]), "r"(a[3]), "r"(b0), "r"(b1));
}
__device__ __forceinline__ void cp_async16(uint32_t saddr, const void* gptr) {
    asm volatile("cp.async.cg.shared.global [%0], [%1], 16;" :: "r"(saddr), "l"(gptr));
}
#define CP_COMMIT() asm volatile("cp.async.commit_group;")
#define CP_WAIT(n)  asm volatile("cp.async.wait_group %0;" :: "n"(n))

// ==================== init ====================
__global__ void k_init() {
    int t = threadIdx.x;
    if (t < 3) g_acc[t] = 0.0;
    if (t < BATCH) g_ccnt[t] = 0;
}

// ==================== fused corner response ====================
// One kernel: gray -> sobel(edge pad) -> products -> gauss7 H (reflect) -> gauss7 V (reflect) -> GFTT resp.
// Tile 32x32 outputs; gray halo 40x40; products/H halo rows 38.
#define GT 40
#define PT 38
__global__ void __launch_bounds__(256) k_corner1(const float* __restrict__ imgs) {
    __shared__ float sg[GT][GT+1];
    __shared__ float sp0[PT][PT+1], sp1[PT][PT+1], sp2[PT][PT+1];
    __shared__ float sh0[PT][33], sh1[PT][33], sh2[PT][33];

    int tile = blockIdx.x;                 // 0..143 (12x12 tiles)
    int b = blockIdx.y;
    int tx = (tile % 12) * 32, ty = (tile / 12) * 32;
    int tid = threadIdx.x;
    const float* im = imgs + (size_t)b * 3 * HW;

    // gray halo: abs coords (ty-4+hr, tx-4+hc), clamped (sobel edge pad)
    for (int idx = tid; idx < GT*GT; idx += 256) {
        int hr = idx / GT, hc = idx % GT;
        int y = ty - 4 + hr; y = y < 0 ? 0 : (y > HDIM-1 ? HDIM-1 : y);
        int x = tx - 4 + hc; x = x < 0 ? 0 : (x > WDIM-1 ? WDIM-1 : x);
        int p = y*WDIM + x;
        sg[hr][hc] = 0.299f*im[p] + 0.587f*im[HW+p] + 0.114f*im[2*HW+p];
    }
    __syncthreads();

    // products at reflected coords (gauss reflect pad happens here)
    for (int idx = tid; idx < PT*PT; idx += 256) {
        int hr = idx / PT, hc = idx % PT;
        int ay = rfl(ty - 3 + hr, HDIM);
        int ax = rfl(tx - 3 + hc, WDIM);
        int ym = ay > 0 ? ay-1 : 0, yp = ay < HDIM-1 ? ay+1 : HDIM-1;
        int xm = ax > 0 ? ax-1 : 0, xp = ax < WDIM-1 ? ax+1 : WDIM-1;
        int gym = ym - (ty-4), gy = ay - (ty-4), gyp = yp - (ty-4);
        int gxm = xm - (tx-4), gx = ax - (tx-4), gxp = xp - (tx-4);
        float a00 = sg[gym][gxm], a01 = sg[gym][gx], a02 = sg[gym][gxp];
        float a10 = sg[gy ][gxm],                    a12 = sg[gy ][gxp];
        float a20 = sg[gyp][gxm], a21 = sg[gyp][gx], a22 = sg[gyp][gxp];
        float dx = (a02 - a00 + 2.f*(a12 - a10) + a22 - a20) * 0.125f;
        float dy = (a20 - a00 + 2.f*(a21 - a01) + a22 - a02) * 0.125f;
        sp0[hr][hc] = dx*dx; sp1[hr][hc] = dy*dy; sp2[hr][hc] = dx*dy;
    }
    __syncthreads();

    // horizontal gauss: 38 rows x 32 cols
    for (int idx = tid; idx < PT*32; idx += 256) {
        int r = idx >> 5, c = idx & 31;
        float s0 = 0.f, s1 = 0.f, s2 = 0.f;
        #pragma unroll
        for (int v = 0; v < 7; v++) {
            float w = GW[v];
            s0 += w * sp0[r][c+v];
            s1 += w * sp1[r][c+v];
            s2 += w * sp2[r][c+v];
        }
        sh0[r][c] = s0; sh1[r][c] = s1; sh2[r][c] = s2;
    }
    __syncthreads();

    // vertical gauss + GFTT response
    for (int idx = tid; idx < 1024; idx += 256) {
        int r = idx >> 5, c = idx & 31;
        float s0 = 0.f, s1 = 0.f, s2 = 0.f;
        #pragma unroll
        for (int v = 0; v < 7; v++) {
            float w = GW[v];
            s0 += w * sh0[r+v][c];
            s1 += w * sh1[r+v][c];
            s2 += w * sh2[r+v][c];
        }
        float tr = s0 + s1;
        float det = s0*s1 - s2*s2;
        g_resp[(size_t)b*HW + (ty+r)*WDIM + (tx+c)] =
            0.5f * (tr - sqrtf(fabsf(tr*tr - 4.f*det)));
    }
}

// ==================== fused NMS + block-max candidates ====================
__global__ void __launch_bounds__(256) k_nmscand() {
    __shared__ float sr[36][37];
    __shared__ float sn[32][33];
    int tile = blockIdx.x, b = blockIdx.y;
    int tx = (tile % 12) * 32, ty = (tile / 12) * 32;
    int tid = threadIdx.x;

    for (int idx = tid; idx < 36*36; idx += 256) {
        int hr = idx / 36, hc = idx % 36;
        int y = ty - 2 + hr, x = tx - 2 + hc;
        sr[hr][hc] = (y >= 0 && y < HDIM && x >= 0 && x < WDIM)
                   ? g_resp[(size_t)b*HW + y*WDIM + x] : -INFINITY;
    }
    __syncthreads();

    for (int idx = tid; idx < 1024; idx += 256) {
        int r = idx >> 5, c = idx & 31;
        float v = sr[r+2][c+2];
        float m = -INFINITY;
        #pragma unroll
        for (int dy = 0; dy < 5; dy++)
            #pragma unroll
            for (int dx = 0; dx < 5; dx++)
                m = fmaxf(m, sr[r+dy][c+dx]);
        sn[r][c] = (v == m) ? v : 0.f;
    }
    __syncthreads();

    int wid = tid >> 5, lane = tid & 31;
    for (int sb = wid; sb < 16; sb += 8) {
        int sby = sb >> 2, sbx = sb & 3;
        float v[2]; int pp[2];
        #pragma unroll
        for (int t = 0; t < 2; t++) {
            int e = lane + 32*t;
            int ly = e >> 3, lx = e & 7;
            v[t] = sn[sby*8 + ly][sbx*8 + lx];
            pp[t] = (ty + sby*8 + ly)*WDIM + (tx + sbx*8 + lx);
        }
        float m = fmaxf(v[0], v[1]);
        #pragma unroll
        for (int off = 16; off > 0; off >>= 1)
            m = fmaxf(m, __shfl_xor_sync(0xFFFFFFFFu, m, off));
        #pragma unroll
        for (int t = 0; t < 2; t++) {
            if (v[t] == m && v[t] > 0.f) {
                int pos = atomicAdd(&g_ccnt[b], 1);
                if (pos < CAND_CAP) {
                    g_cval[b*CAND_CAP + pos] = v[t];
                    g_cidx[b*CAND_CAP + pos] = pp[t];
                }
            }
        }
    }
}

// ==================== top-200 + corner-sum ====================
__global__ void __launch_bounds__(1024) k_topk(const float* __restrict__ sd) {
    __shared__ unsigned long long keys[CAND_CAP];
    int b = blockIdx.x;
    int tid = threadIdx.x;
    int n = g_ccnt[b]; if (n > CAND_CAP) n = CAND_CAP;
    for (int i = tid; i < CAND_CAP; i += 1024) {
        unsigned long long kk = 0ull;
        if (i < n) {
            unsigned int vb = __float_as_uint(g_cval[b*CAND_CAP + i]);
            kk = ((unsigned long long)vb << 32) | (unsigned long long)(0xFFFFFFFFu - (unsigned)g_cidx[b*CAND_CAP + i]);
        }
        keys[i] = kk;
    }
    __syncthreads();
    for (int k = 2; k <= CAND_CAP; k <<= 1) {
        for (int j = k >> 1; j > 0; j >>= 1) {
            for (int i = tid; i < CAND_CAP; i += 1024) {
                int ixj = i ^ j;
                if (ixj > i) {
                    bool descend = ((i & k) == 0);
                    unsigned long long a = keys[i], c = keys[ixj];
                    if (descend ? (a < c) : (a > c)) { keys[i] = c; keys[ixj] = a; }
                }
            }
            __syncthreads();
        }
    }
    int take = n < NUMK ? n : NUMK;
    double s = 0.0;
    if (tid < take) {
        unsigned idx = 0xFFFFFFFFu - (unsigned)(keys[tid] & 0xFFFFFFFFull);
        s = (double)sd[(size_t)b*HW + idx];
    }
    __shared__ double red[32];
    #pragma unroll
    for (int off = 16; off > 0; off >>= 1) s += __shfl_xor_sync(0xFFFFFFFFu, s, off);
    if ((tid & 31) == 0) red[tid >> 5] = s;
    __syncthreads();
    if (tid < 32) {
        double v = red[tid];
        #pragma unroll
        for (int off = 16; off > 0; off >>= 1) v += __shfl_xor_sync(0xFFFFFFFFu, v, off);
        if (tid == 0) atomicAdd(&g_acc[1], v);
    }
}

__global__ void k_logexp(const float* __restrict__ sd) {
    double s = 0.0;
    int stride = gridDim.x * blockDim.x;
    for (int i = blockIdx.x * blockDim.x + threadIdx.x; i < BATCH*HW; i += stride) {
        float v = sd[i];
        s += (double)(fmaxf(v, 0.f) + log1pf(expf(-fabsf(v))));
    }
    __shared__ double red[8];
    #pragma unroll
    for (int off = 16; off > 0; off >>= 1) s += __shfl_xor_sync(0xFFFFFFFFu, s, off);
    int t = threadIdx.x;
    if ((t & 31) == 0) red[t >> 5] = s;
    __syncthreads();
    if (t < 8) {
        double v = red[t];
        #pragma unroll
        for (int off = 4; off > 0; off >>= 1) v += __shfl_xor_sync(0xFFu, v, off);
        if (t == 0) atomicAdd(&g_acc[0], v);
    }
}

// ==================== descriptor prep: normalize -> bf16 ====================
__global__ void k_prep(const float* __restrict__ desc) {
    int gw = (blockIdx.x * blockDim.x + threadIdx.x) >> 5;
    int lane = threadIdx.x & 31;
    if (gw >= BATCH*NPT) return;
    const float* p = desc + (size_t)gw * DDIM;
    float v[8]; float s = 0.f;
    #pragma unroll
    for (int t = 0; t < 8; t++) { v[t] = p[lane + 32*t]; s += v[t]*v[t]; }
    #pragma unroll
    for (int off = 16; off > 0; off >>= 1) s += __shfl_xor_sync(0xFFFFFFFFu, s, off);
    float inv = 1.f / fmaxf(sqrtf(s), 1e-8f);
    __nv_bfloat16* q = g_descbf + (size_t)gw * DDIM;
    #pragma unroll
    for (int t = 0; t < 8; t++) q[lane + 32*t] = __float2bfloat16(v[t] * inv);
}

// ==================== bf16 HMMA symmetric GEMM (cp.async 2-stage) ====================
// CTA 128x128, 8 warps (2x4), warp = 64x32 via m16n8k16.
// Dynamic smem: align1024(base) -> [A0 16K][B0 16K][A1 16K][B1 16K]
#define GEMM_DSMEM (1024 + 4*STAGE_BYTES)
__global__ void __launch_bounds__(256) k_gemm_mma() {
    extern __shared__ char dsm[];
    __shared__ double red[8];
    uint32_t base_u = smem_to_u32(dsm);
    uint32_t s0 = (base_u + 1023u) & ~1023u;

    int tid = threadIdx.x, wid = tid >> 5, lane = tid & 31;
    int wm = wid & 1, wn = wid >> 1;       // warp grid 2(M) x 4(N)
    int b = blockIdx.y;
    int ti = 0, rem = blockIdx.x;
    while (rem >= NT2 - ti) { rem -= NT2 - ti; ti++; }
    int tj = ti + rem;

    const __nv_bfloat16* Abase = g_descbf + ((size_t)b*NPT + (size_t)ti*TM) * DDIM;
    const __nv_bfloat16* Bbase = g_descbf + ((size_t)b*NPT + (size_t)tj*TM) * DDIM;

    int lrow = lane & 15, lkh = lane >> 4;
    int ldrow = tid >> 3, ldseg = tid & 7;

    float acc[4][4][4];
    #pragma unroll
    for (int i = 0; i < 4; i++)
        #pragma unroll
        for (int j = 0; j < 4; j++)
            #pragma unroll
            for (int c = 0; c < 4; c++) acc[i][j][c] = 0.f;

    // prefetch helper (stage st gets chunk kc)
    auto prefetch = [&](int kc, int st) {
        uint32_t sa = s0 + st*2*STAGE_BYTES;
        uint32_t sb = sa + STAGE_BYTES;
        #pragma unroll
        for (int u = 0; u < 4; u++) {
            int row = ldrow + u*32;
            uint32_t off = SMEM_SWIZZLE_128B((uint32_t)(row*128 + ldseg*16));
            cp_async16(sa + off, Abase + (size_t)row*DDIM + kc*KC + ldseg*8);
            cp_async16(sb + off, Bbase + (size_t)row*DDIM + kc*KC + ldseg*8);
        }
    };

    prefetch(0, 0);
    CP_COMMIT();

    for (int kc = 0; kc < NCHUNK; kc++) {
        if (kc + 1 < NCHUNK) {
            prefetch(kc + 1, (kc + 1) & 1);
            CP_COMMIT();
            CP_WAIT(1);
        } else {
            CP_WAIT(0);
        }
        __syncthreads();

        uint32_t sAu = s0 + (kc & 1)*2*STAGE_BYTES;
        uint32_t sBu = sAu + STAGE_BYTES;

        #pragma unroll
        for (int ks = 0; ks < 4; ks++) {
            uint32_t bf[2][4];
            #pragma unroll
            for (int np = 0; np < 2; np++) {
                int row = wn*32 + np*16 + lrow;
                uint32_t off = SMEM_SWIZZLE_128B((uint32_t)(row*128 + ks*32 + lkh*16));
                ldm_x4(bf[np][0], bf[np][1], bf[np][2], bf[np][3], sBu + off);
            }
            uint32_t af[4][4];
            #pragma unroll
            for (int i = 0; i < 4; i++) {
                int row = wm*64 + i*16 + lrow;
                uint32_t off = SMEM_SWIZZLE_128B((uint32_t)(row*128 + ks*32 + lkh*16));
                ldm_x4(af[i][0], af[i][1], af[i][2], af[i][3], sAu + off);
            }
            #pragma unroll
            for (int i = 0; i < 4; i++)
                #pragma unroll
                for (int j = 0; j < 4; j++) {
                    int np = j >> 1, h = j & 1;
                    mma_bf16(acc[i][j], af[i], bf[np][h], bf[np][h + 2]);
                }
        }
        __syncthreads();
    }

    // epilogue: relu + symmetry weight + reduce
    double s = 0.0;
    int gi_base = ti*TM + wm*64;
    int gj_base = tj*TN + wn*32;
    int r0 = lane >> 2, c0 = (lane & 3) * 2;
    #pragma unroll
    for (int i = 0; i < 4; i++) {
        #pragma unroll
        for (int j = 0; j < 4; j++) {
            #pragma unroll
            for (int c = 0; c < 4; c++) {
                float v = acc[i][j][c];
                float r = v > 0.f ? v : 0.f;
                if (ti != tj) {
                    s += (double)(2.f * r);
                } else {
                    int gi = gi_base + i*16 + r0 + ((c >> 1) ? 8 : 0);
                    int gj = gj_base + j*8 + c0 + (c & 1);
                    float w = (gi < gj) ? 2.f : (gi == gj ? 1.f : 0.f);
                    s += (double)(w * r);
                }
            }
        }
    }
    #pragma unroll
    for (int off = 16; off > 0; off >>= 1) s += __shfl_xor_sync(0xFFFFFFFFu, s, off);
    if (lane == 0) red[wid] = s;
    __syncthreads();
    if (tid < 8) {
        double v = red[tid];
        #pragma unroll
        for (int off = 4; off > 0; off >>= 1) v += __shfl_xor_sync(0xFFu, v, off);
        if (tid == 0) atomicAdd(&g_acc[2], v);
    }
}

__global__ void k_final(float* out) {
    double bce = (g_acc[0] - g_acc[1]) / (double)((size_t)BATCH * HW);
    double rel = g_acc[2] / ((double)BATCH * (double)NPT * (double)NPT);
    out[0] = (float)(bce + rel);
}

extern "C" void kernel_launch(void* const* d_in, const int* in_sizes, int n_in,
                              void* d_out, int out_size) {
    const float* desc = (const float*)d_in[0];
    // d_in[1] = scores (unused by the reference loss)
    const float* sd   = (const float*)d_in[2];
    const float* imgs = (const float*)d_in[3];
    float* out = (float*)d_out;

    // Not a stream op; safe under graph capture. Called unconditionally (no static guards).
    cudaFuncSetAttribute(k_gemm_mma, cudaFuncAttributeMaxDynamicSharedMemorySize, GEMM_DSMEM);

    k_init<<<1, 32>>>();
    {
        dim3 grid(144, BATCH);
        k_corner1<<<grid, 256>>>(imgs);
        k_nmscand<<<grid, 256>>>();
    }
    k_topk<<<BATCH, 1024>>>(sd);
    k_logexp<<<1024, 256>>>(sd);
    {
        const int warps = BATCH * NPT;                       // 32768
        k_prep<<<(warps*32 + 255) / 256, 256>>>(desc);
    }
    {
        dim3 grid(NPAIRS2, BATCH);
        k_gemm_mma<<<grid, 256, GEMM_DSMEM>>>();
    }
    k_final<<<1, 1>>>(out);
    (void)in_sizes; (void)n_in; (void)out_size;
}

// round 10
// speedup vs baseline: 2.4048x; 1.1015x over previous
#include <cuda_runtime.h>
#include <cuda_bf16.h>
#include <math.h>
#include <cstdint>

// Problem constants
#define BATCH 16
#define HDIM 384
#define WDIM 384
#define HW (HDIM*WDIM)          // 147456
#define NPT 2048
#define DDIM 256
#define NUMK 200
#define CAND_CAP 4096

// GEMM tiling (HMMA mma.sync path; tcgen05 unavailable: harness targets compute_103 non-'a')
#define TM 128
#define TN 128
#define KC 64                   // bf16 per K-chunk (128 bytes/row)
#define NCHUNK (DDIM/KC)        // 4
#define NT2 (NPT/TM)            // 16
#define NPAIRS2 (NT2*(NT2+1)/2) // 136
#define STAGE_BYTES (TM*128)    // 16KB per tile per stage

// Scratch (static device globals; allocation-free)
__device__ float g_resp[BATCH*HW];
__device__ float g_cval[BATCH*CAND_CAP];
__device__ int   g_cidx[BATCH*CAND_CAP];
__device__ int   g_ccnt[BATCH];
__device__ double g_acc[3];  // 0: sum log1pexp, 1: sum s at corners, 2: sum weighted relu(cos)
__device__ __nv_bfloat16 g_descbf[(size_t)BATCH*NPT*DDIM];  // 16MB normalized bf16

__device__ __constant__ float GW[7] = {
    0.00443304997f, 0.05400558296f, 0.24203622937f, 0.39905027540f,
    0.24203622937f, 0.05400558296f, 0.00443304997f
};

#define SMEM_SWIZZLE_128B(byte_offset) \
    ((byte_offset) ^ (((byte_offset) >> 3) & 0x70))

__device__ __forceinline__ int rfl(int i, int n) {
    if (i < 0) i = -i;
    if (i >= n) i = 2*n - 2 - i;
    return i;
}
__device__ __forceinline__ uint32_t smem_to_u32(const void* smem_ptr) {
    uint32_t addr;
    asm("{ .reg .u64 tmp; cvta.to.shared.u64 tmp, %1; cvt.u32.u64 %0, tmp; }"
        : "=r"(addr) : "l"(smem_ptr));
    return addr;
}
__device__ __forceinline__ void ldm_x4(uint32_t& r0, uint32_t& r1, uint32_t& r2, uint32_t& r3,
                                       uint32_t addr) {
    asm volatile("ldmatrix.sync.aligned.m8n8.x4.shared.b16 {%0,%1,%2,%3}, [%4];"
                 : "=r"(r0), "=r"(r1), "=r"(r2), "=r"(r3) : "r"(addr));
}
__device__ __forceinline__ void mma_bf16(float* c, const uint32_t* a, uint32_t b0, uint32_t b1) {
    asm volatile(
        "mma.sync.aligned.m16n8k16.row.col.f32.bf16.bf16.f32 "
        "{%0,%1,%2,%3}, {%4,%5,%6,%7}, {%8,%9}, {%0,%1,%2,%3};"
        : "+f"(c[0]), "+f"(c[1]), "+f"(c[2]), "+f"(c[3])
        : "r"(a[0]), "r"(a[1]), "r"(a[2]), "r"(a[3]), "r"(b0), "r"(b1));
}
__device__ __forceinline__ void cp_async16(uint32_t saddr, const void* gptr) {
    asm volatile("cp.async.cg.shared.global [%0], [%1], 16;" :: "r"(saddr), "l"(gptr));
}
#define CP_COMMIT() asm volatile("cp.async.commit_group;")
#define CP_WAIT(n)  asm volatile("cp.async.wait_group %0;" :: "n"(n))

// ==================== init ====================
__global__ void k_init() {
    int t = threadIdx.x;
    if (t < 3) g_acc[t] = 0.0;
    if (t < BATCH) g_ccnt[t] = 0;
}

// ==================== fused corner response ====================
#define GT 40
#define PT 38
__global__ void __launch_bounds__(256) k_corner1(const float* __restrict__ imgs) {
    __shared__ float sg[GT][GT+1];
    __shared__ float sp0[PT][PT+1], sp1[PT][PT+1], sp2[PT][PT+1];
    __shared__ float sh0[PT][33], sh1[PT][33], sh2[PT][33];

    int tile = blockIdx.x;                 // 0..143 (12x12 tiles)
    int b = blockIdx.y;
    int tx = (tile % 12) * 32, ty = (tile / 12) * 32;
    int tid = threadIdx.x;
    const float* im = imgs + (size_t)b * 3 * HW;

    for (int idx = tid; idx < GT*GT; idx += 256) {
        int hr = idx / GT, hc = idx % GT;
        int y = ty - 4 + hr; y = y < 0 ? 0 : (y > HDIM-1 ? HDIM-1 : y);
        int x = tx - 4 + hc; x = x < 0 ? 0 : (x > WDIM-1 ? WDIM-1 : x);
        int p = y*WDIM + x;
        sg[hr][hc] = 0.299f*im[p] + 0.587f*im[HW+p] + 0.114f*im[2*HW+p];
    }
    __syncthreads();

    for (int idx = tid; idx < PT*PT; idx += 256) {
        int hr = idx / PT, hc = idx % PT;
        int ay = rfl(ty - 3 + hr, HDIM);
        int ax = rfl(tx - 3 + hc, WDIM);
        int ym = ay > 0 ? ay-1 : 0, yp = ay < HDIM-1 ? ay+1 : HDIM-1;
        int xm = ax > 0 ? ax-1 : 0, xp = ax < WDIM-1 ? ax+1 : WDIM-1;
        int gym = ym - (ty-4), gy = ay - (ty-4), gyp = yp - (ty-4);
        int gxm = xm - (tx-4), gx = ax - (tx-4), gxp = xp - (tx-4);
        float a00 = sg[gym][gxm], a01 = sg[gym][gx], a02 = sg[gym][gxp];
        float a10 = sg[gy ][gxm],                    a12 = sg[gy ][gxp];
        float a20 = sg[gyp][gxm], a21 = sg[gyp][gx], a22 = sg[gyp][gxp];
        float dx = (a02 - a00 + 2.f*(a12 - a10) + a22 - a20) * 0.125f;
        float dy = (a20 - a00 + 2.f*(a21 - a01) + a22 - a02) * 0.125f;
        sp0[hr][hc] = dx*dx; sp1[hr][hc] = dy*dy; sp2[hr][hc] = dx*dy;
    }
    __syncthreads();

    for (int idx = tid; idx < PT*32; idx += 256) {
        int r = idx >> 5, c = idx & 31;
        float s0 = 0.f, s1 = 0.f, s2 = 0.f;
        #pragma unroll
        for (int v = 0; v < 7; v++) {
            float w = GW[v];
            s0 += w * sp0[r][c+v];
            s1 += w * sp1[r][c+v];
            s2 += w * sp2[r][c+v];
        }
        sh0[r][c] = s0; sh1[r][c] = s1; sh2[r][c] = s2;
    }
    __syncthreads();

    for (int idx = tid; idx < 1024; idx += 256) {
        int r = idx >> 5, c = idx & 31;
        float s0 = 0.f, s1 = 0.f, s2 = 0.f;
        #pragma unroll
        for (int v = 0; v < 7; v++) {
            float w = GW[v];
            s0 += w * sh0[r+v][c];
            s1 += w * sh1[r+v][c];
            s2 += w * sh2[r+v][c];
        }
        float tr = s0 + s1;
        float det = s0*s1 - s2*s2;
        g_resp[(size_t)b*HW + (ty+r)*WDIM + (tx+c)] =
            0.5f * (tr - sqrtf(fabsf(tr*tr - 4.f*det)));
    }
}

// ==================== fused NMS + block-max candidates ====================
__global__ void __launch_bounds__(256) k_nmscand() {
    __shared__ float sr[36][37];
    __shared__ float sn[32][33];
    int tile = blockIdx.x, b = blockIdx.y;
    int tx = (tile % 12) * 32, ty = (tile / 12) * 32;
    int tid = threadIdx.x;

    for (int idx = tid; idx < 36*36; idx += 256) {
        int hr = idx / 36, hc = idx % 36;
        int y = ty - 2 + hr, x = tx - 2 + hc;
        sr[hr][hc] = (y >= 0 && y < HDIM && x >= 0 && x < WDIM)
                   ? g_resp[(size_t)b*HW + y*WDIM + x] : -INFINITY;
    }
    __syncthreads();

    for (int idx = tid; idx < 1024; idx += 256) {
        int r = idx >> 5, c = idx & 31;
        float v = sr[r+2][c+2];
        float m = -INFINITY;
        #pragma unroll
        for (int dy = 0; dy < 5; dy++)
            #pragma unroll
            for (int dx = 0; dx < 5; dx++)
                m = fmaxf(m, sr[r+dy][c+dx]);
        sn[r][c] = (v == m) ? v : 0.f;
    }
    __syncthreads();

    int wid = tid >> 5, lane = tid & 31;
    for (int sb = wid; sb < 16; sb += 8) {
        int sby = sb >> 2, sbx = sb & 3;
        float v[2]; int pp[2];
        #pragma unroll
        for (int t = 0; t < 2; t++) {
            int e = lane + 32*t;
            int ly = e >> 3, lx = e & 7;
            v[t] = sn[sby*8 + ly][sbx*8 + lx];
            pp[t] = (ty + sby*8 + ly)*WDIM + (tx + sbx*8 + lx);
        }
        float m = fmaxf(v[0], v[1]);
        #pragma unroll
        for (int off = 16; off > 0; off >>= 1)
            m = fmaxf(m, __shfl_xor_sync(0xFFFFFFFFu, m, off));
        #pragma unroll
        for (int t = 0; t < 2; t++) {
            if (v[t] == m && v[t] > 0.f) {
                int pos = atomicAdd(&g_ccnt[b], 1);
                if (pos < CAND_CAP) {
                    g_cval[b*CAND_CAP + pos] = v[t];
                    g_cidx[b*CAND_CAP + pos] = pp[t];
                }
            }
        }
    }
}

// ==================== top-200 via 4-pass radix select + corner-sum ====================
// Candidates are all > 0 so float order == uint-bits order.
__global__ void __launch_bounds__(256) k_topk(const float* __restrict__ sd) {
    __shared__ int hist[256];
    __shared__ int sufx[256];
    __shared__ unsigned sh_prefix;
    __shared__ int sh_need;
    __shared__ int tcnt;
    __shared__ int tie_idx[1024];
    __shared__ int curmin;
    __shared__ double red[8];

    int b = blockIdx.x;
    int tid = threadIdx.x;
    int n = g_ccnt[b]; if (n > CAND_CAP) n = CAND_CAP;
    const float* cval = g_cval + b*CAND_CAP;
    const int*   cidx = g_cidx + b*CAND_CAP;
    const float* sdb = sd + (size_t)b*HW;

    double s = 0.0;
    if (n <= NUMK) {
        for (int i = tid; i < n; i += 256) s += (double)sdb[cidx[i]];
    } else {
        if (tid == 0) { sh_prefix = 0u; sh_need = NUMK; }
        __syncthreads();
        #pragma unroll
        for (int pass = 0; pass < 4; pass++) {
            int shift = 24 - pass*8;
            unsigned pmask = (pass == 0) ? 0u : (0xFFFFFFFFu << (shift + 8));
            hist[tid] = 0;
            __syncthreads();
            unsigned prefix = sh_prefix;
            for (int i = tid; i < n; i += 256) {
                unsigned bits = __float_as_uint(cval[i]);
                if ((bits & pmask) == prefix)
                    atomicAdd(&hist[(bits >> shift) & 255], 1);
            }
            __syncthreads();
            // suffix sums: sufx[t] = sum_{u>=t} hist[u]
            sufx[tid] = hist[tid];
            __syncthreads();
            #pragma unroll
            for (int off = 1; off < 256; off <<= 1) {
                int v = (tid + off < 256) ? sufx[tid + off] : 0;
                __syncthreads();
                sufx[tid] += v;
                __syncthreads();
            }
            int need = sh_need;
            int gt = (tid + 1 < 256) ? sufx[tid + 1] : 0;
            if (gt < need && need <= gt + hist[tid]) {   // exactly one thread matches
                sh_prefix = prefix | ((unsigned)tid << shift);
                sh_need = need - gt;
            }
            __syncthreads();
        }
        unsigned T = sh_prefix;
        int need = sh_need;                 // how many to take at value T
        if (tid == 0) tcnt = 0;
        __syncthreads();
        for (int i = tid; i < n; i += 256) {
            unsigned bits = __float_as_uint(cval[i]);
            if (bits > T) {
                s += (double)sdb[cidx[i]];
            } else if (bits == T) {
                int p = atomicAdd(&tcnt, 1);
                if (p < 1024) tie_idx[p] = cidx[i];
            }
        }
        __syncthreads();
        int cnt = tcnt; if (cnt > 1024) cnt = 1024;
        if (cnt <= need) {
            for (int i = tid; i < cnt; i += 256) s += (double)sdb[tie_idx[i]];
        } else {
            // take `need` smallest indices among ties (matches top_k stability)
            for (int k = 0; k < need; k++) {
                if (tid == 0) curmin = 0x7FFFFFFF;
                __syncthreads();
                int loc = 0x7FFFFFFF;
                for (int i = tid; i < cnt; i += 256) loc = min(loc, tie_idx[i]);
                atomicMin(&curmin, loc);
                __syncthreads();
                int mv = curmin;
                if (tid == 0) s += (double)sdb[mv];
                for (int i = tid; i < cnt; i += 256)
                    if (tie_idx[i] == mv) tie_idx[i] = 0x7FFFFFFF;
                __syncthreads();
            }
        }
    }
    // block reduce
    #pragma unroll
    for (int off = 16; off > 0; off >>= 1) s += __shfl_xor_sync(0xFFFFFFFFu, s, off);
    int wid = tid >> 5;
    if ((tid & 31) == 0) red[wid] = s;
    __syncthreads();
    if (tid < 8) {
        double v = red[tid];
        #pragma unroll
        for (int off = 4; off > 0; off >>= 1) v += __shfl_xor_sync(0xFFu, v, off);
        if (tid == 0) atomicAdd(&g_acc[1], v);
    }
}

__global__ void k_logexp(const float* __restrict__ sd) {
    double s = 0.0;
    int stride = gridDim.x * blockDim.x;
    for (int i = blockIdx.x * blockDim.x + threadIdx.x; i < BATCH*HW; i += stride) {
        float v = sd[i];
        // logaddexp(0,v) = max(v,0) + log(1 + exp(-|v|)); fast MUFU path
        s += (double)(fmaxf(v, 0.f) + __logf(1.f + __expf(-fabsf(v))));
    }
    __shared__ double red[8];
    #pragma unroll
    for (int off = 16; off > 0; off >>= 1) s += __shfl_xor_sync(0xFFFFFFFFu, s, off);
    int t = threadIdx.x;
    if ((t & 31) == 0) red[t >> 5] = s;
    __syncthreads();
    if (t < 8) {
        double v = red[t];
        #pragma unroll
        for (int off = 4; off > 0; off >>= 1) v += __shfl_xor_sync(0xFFu, v, off);
        if (t == 0) atomicAdd(&g_acc[0], v);
    }
}

// ==================== descriptor prep: normalize -> bf16 ====================
__global__ void k_prep(const float* __restrict__ desc) {
    int gw = (blockIdx.x * blockDim.x + threadIdx.x) >> 5;
    int lane = threadIdx.x & 31;
    if (gw >= BATCH*NPT) return;
    const float* p = desc + (size_t)gw * DDIM;
    float v[8]; float s = 0.f;
    #pragma unroll
    for (int t = 0; t < 8; t++) { v[t] = p[lane + 32*t]; s += v[t]*v[t]; }
    #pragma unroll
    for (int off = 16; off > 0; off >>= 1) s += __shfl_xor_sync(0xFFFFFFFFu, s, off);
    float inv = 1.f / fmaxf(sqrtf(s), 1e-8f);
    __nv_bfloat16* q = g_descbf + (size_t)gw * DDIM;
    #pragma unroll
    for (int t = 0; t < 8; t++) q[lane + 32*t] = __float2bfloat16(v[t] * inv);
}

// ==================== bf16 HMMA symmetric GEMM (cp.async 2-stage) ====================
#define GEMM_DSMEM (1024 + 4*STAGE_BYTES)
__global__ void __launch_bounds__(256) k_gemm_mma() {
    extern __shared__ char dsm[];
    __shared__ double red[8];
    uint32_t base_u = smem_to_u32(dsm);
    uint32_t s0 = (base_u + 1023u) & ~1023u;

    int tid = threadIdx.x, wid = tid >> 5, lane = tid & 31;
    int wm = wid & 1, wn = wid >> 1;       // warp grid 2(M) x 4(N)
    int b = blockIdx.y;
    int ti = 0, rem = blockIdx.x;
    while (rem >= NT2 - ti) { rem -= NT2 - ti; ti++; }
    int tj = ti + rem;

    const __nv_bfloat16* Abase = g_descbf + ((size_t)b*NPT + (size_t)ti*TM) * DDIM;
    const __nv_bfloat16* Bbase = g_descbf + ((size_t)b*NPT + (size_t)tj*TM) * DDIM;

    int lrow = lane & 15, lkh = lane >> 4;
    int ldrow = tid >> 3, ldseg = tid & 7;

    float acc[4][4][4];
    #pragma unroll
    for (int i = 0; i < 4; i++)
        #pragma unroll
        for (int j = 0; j < 4; j++)
            #pragma unroll
            for (int c = 0; c < 4; c++) acc[i][j][c] = 0.f;

    auto prefetch = [&](int kc, int st) {
        uint32_t sa = s0 + st*2*STAGE_BYTES;
        uint32_t sb = sa + STAGE_BYTES;
        #pragma unroll
        for (int u = 0; u < 4; u++) {
            int row = ldrow + u*32;
            uint32_t off = SMEM_SWIZZLE_128B((uint32_t)(row*128 + ldseg*16));
            cp_async16(sa + off, Abase + (size_t)row*DDIM + kc*KC + ldseg*8);
            cp_async16(sb + off, Bbase + (size_t)row*DDIM + kc*KC + ldseg*8);
        }
    };

    prefetch(0, 0);
    CP_COMMIT();

    for (int kc = 0; kc < NCHUNK; kc++) {
        if (kc + 1 < NCHUNK) {
            prefetch(kc + 1, (kc + 1) & 1);
            CP_COMMIT();
            CP_WAIT(1);
        } else {
            CP_WAIT(0);
        }
        __syncthreads();

        uint32_t sAu = s0 + (kc & 1)*2*STAGE_BYTES;
        uint32_t sBu = sAu + STAGE_BYTES;

        #pragma unroll
        for (int ks = 0; ks < 4; ks++) {
            uint32_t bf[2][4];
            #pragma unroll
            for (int np = 0; np < 2; np++) {
                int row = wn*32 + np*16 + lrow;
                uint32_t off = SMEM_SWIZZLE_128B((uint32_t)(row*128 + ks*32 + lkh*16));
                ldm_x4(bf[np][0], bf[np][1], bf[np][2], bf[np][3], sBu + off);
            }
            uint32_t af[4][4];
            #pragma unroll
            for (int i = 0; i < 4; i++) {
                int row = wm*64 + i*16 + lrow;
                uint32_t off = SMEM_SWIZZLE_128B((uint32_t)(row*128 + ks*32 + lkh*16));
                ldm_x4(af[i][0], af[i][1], af[i][2], af[i][3], sAu + off);
            }
            #pragma unroll
            for (int i = 0; i < 4; i++)
                #pragma unroll
                for (int j = 0; j < 4; j++) {
                    int np = j >> 1, h = j & 1;
                    mma_bf16(acc[i][j], af[i], bf[np][h], bf[np][h + 2]);
                }
        }
        __syncthreads();
    }

    // epilogue: relu + symmetry weight + reduce
    double s = 0.0;
    int gi_base = ti*TM + wm*64;
    int gj_base = tj*TN + wn*32;
    int r0 = lane >> 2, c0 = (lane & 3) * 2;
    #pragma unroll
    for (int i = 0; i < 4; i++) {
        #pragma unroll
        for (int j = 0; j < 4; j++) {
            #pragma unroll
            for (int c = 0; c < 4; c++) {
                float v = acc[i][j][c];
                float r = v > 0.f ? v : 0.f;
                if (ti != tj) {
                    s += (double)(2.f * r);
                } else {
                    int gi = gi_base + i*16 + r0 + ((c >> 1) ? 8 : 0);
                    int gj = gj_base + j*8 + c0 + (c & 1);
                    float w = (gi < gj) ? 2.f : (gi == gj ? 1.f : 0.f);
                    s += (double)(w * r);
                }
            }
        }
    }
    #pragma unroll
    for (int off = 16; off > 0; off >>= 1) s += __shfl_xor_sync(0xFFFFFFFFu, s, off);
    if (lane == 0) red[wid] = s;
    __syncthreads();
    if (tid < 8) {
        double v = red[tid];
        #pragma unroll
        for (int off = 4; off > 0; off >>= 1) v += __shfl_xor_sync(0xFFu, v, off);
        if (tid == 0) atomicAdd(&g_acc[2], v);
    }
}

__global__ void k_final(float* out) {
    double bce = (g_acc[0] - g_acc[1]) / (double)((size_t)BATCH * HW);
    double rel = g_acc[2] / ((double)BATCH * (double)NPT * (double)NPT);
    out[0] = (float)(bce + rel);
}

extern "C" void kernel_launch(void* const* d_in, const int* in_sizes, int n_in,
                              void* d_out, int out_size) {
    const float* desc = (const float*)d_in[0];
    // d_in[1] = scores (unused by the reference loss)
    const float* sd   = (const float*)d_in[2];
    const float* imgs = (const float*)d_in[3];
    float* out = (float*)d_out;

    // Not a stream op; safe under graph capture. Called unconditionally (no static guards).
    cudaFuncSetAttribute(k_gemm_mma, cudaFuncAttributeMaxDynamicSharedMemorySize, GEMM_DSMEM);

    k_init<<<1, 32>>>();
    {
        dim3 grid(144, BATCH);
        k_corner1<<<grid, 256>>>(imgs);
        k_nmscand<<<grid, 256>>>();
    }
    k_topk<<<BATCH, 256>>>(sd);
    k_logexp<<<1024, 256>>>(sd);
    {
        const int warps = BATCH * NPT;                       // 32768
        k_prep<<<(warps*32 + 255) / 256, 256>>>(desc);
    }
    {
        dim3 grid(NPAIRS2, BATCH);
        k_gemm_mma<<<grid, 256, GEMM_DSMEM>>>();
    }
    k_final<<<1, 1>>>(out);
    (void)in_sizes; (void)n_in; (void)out_size;
}